// round 10
// baseline (speedup 1.0000x reference)
#include <cuda_runtime.h>
#include <cuda_fp16.h>
#include <cstdint>

#define N_NODES 50000
#define N_EDGES 800000
#define H 128
#define RDIM 6
#define NTYPES 95
#define NKEYS (NTYPES * 3)      // 285
#define TM 64                   // edges per tile
#define NTILES (N_EDGES / TM)   // 12500
#define GRID 592                // 4 CTAs/SM * 148 SMs

// ---------------------------------------------------------------------------
// scratch (__device__ globals; allocation-free rule)
// ---------------------------------------------------------------------------
__device__ __align__(16) __half g_tableA[NKEYS * H];
__device__ __align__(16) __half g_tableB[NKEYS * H];
__device__ int g_key[N_NODES];

// ---------------------------------------------------------------------------
// helpers
// ---------------------------------------------------------------------------
__device__ __forceinline__ float silu_acc(float v) {        // accurate (epilogue)
    return __fdividef(v, 1.0f + __expf(-v));
}
__device__ __forceinline__ __half2 tanh_h2(__half2 x) {     // tanh.approx.f16x2
    uint32_t r, xi = *reinterpret_cast<uint32_t*>(&x);
    asm("tanh.approx.f16x2 %0, %1;" : "=r"(r) : "r"(xi));
    return *reinterpret_cast<__half2*>(&r);
}
__device__ __forceinline__ uint32_t pack_h2(float lo, float hi) {
    __half2 h = __floats2half2_rn(lo, hi);
    return *reinterpret_cast<uint32_t*>(&h);
}

// fp16 m16n8k16, f32 accumulate
__device__ __forceinline__ void mma_f16(float (&d)[4],
                                        uint32_t a0, uint32_t a1, uint32_t a2, uint32_t a3,
                                        uint32_t b0, uint32_t b1) {
    asm volatile(
        "mma.sync.aligned.m16n8k16.row.col.f32.f16.f16.f32 "
        "{%0,%1,%2,%3}, {%4,%5,%6,%7}, {%8,%9}, {%0,%1,%2,%3};\n"
        : "+f"(d[0]), "+f"(d[1]), "+f"(d[2]), "+f"(d[3])
        : "r"(a0), "r"(a1), "r"(a2), "r"(a3), "r"(b0), "r"(b1));
}

// ---------------------------------------------------------------------------
// kernel 1: key[n] = x[n]*3 + s[n]
// ---------------------------------------------------------------------------
__global__ void key_kernel(const int* __restrict__ x, const int* __restrict__ s) {
    int n = blockIdx.x * blockDim.x + threadIdx.x;
    if (n < N_NODES) g_key[n] = x[n] * 3 + s[n];
}

// ---------------------------------------------------------------------------
// kernel 2: per-(type,spin) tables (fp32 math, stored fp16)
// ---------------------------------------------------------------------------
__global__ void table_kernel(const float* __restrict__ emb_w,
                             const float* __restrict__ spin_w,
                             const float* __restrict__ spin_b,
                             const float* __restrict__ lin_w,
                             const float* __restrict__ lin_b) {
    __shared__ float sh[H];
    const int b = blockIdx.x;
    const int t = b / 3, c = b % 3;
    const int tid = threadIdx.x, lane = tid & 31, w = tid >> 5;
    sh[tid] = emb_w[t * H + tid];
    const float sp0 = spin_w[0 * 3 + c] + spin_b[0];
    const float sp1 = spin_w[1 * 3 + c] + spin_b[1];
    const float sp2 = spin_w[2 * 3 + c] + spin_b[2];
    __syncthreads();
    for (int o = w * 32; o < w * 32 + 32; o++) {
        const float* row = lin_w + o * 390;
        float pa = 0.f, pb = 0.f;
#pragma unroll
        for (int u = 0; u < 4; u++) {
            int k = lane * 4 + u;
            pa += row[k] * sh[k];
            pb += row[131 + k] * sh[k];
        }
#pragma unroll
        for (int d = 16; d > 0; d >>= 1) {
            pa += __shfl_xor_sync(0xffffffffu, pa, d);
            pb += __shfl_xor_sync(0xffffffffu, pb, d);
        }
        if (lane == 0) {
            float sa = sp0 * row[128] + sp1 * row[129] + sp2 * row[130];
            float sb = sp0 * row[259] + sp1 * row[260] + sp2 * row[261];
            g_tableA[b * H + o] = __float2half_rn(pa + sa + lin_b[o]);
            g_tableB[b * H + o] = __float2half_rn(pb + sb);
        }
    }
}

// ---------------------------------------------------------------------------
// kernel 3: persistent edge kernel — fp16 m16n8k16, register epilogue
//
// A fragments (fp16x2 words): block (mt 0..3, kc 0..7) = 132 words (pad 4);
//   word = (mt*8+kc)*132 + lane*4 + reg,  lane = g*4+tg, reg = 2*pb + hi
// W fragments (uint4): [(kc*8+ntp)*32+lane] = {b0,b1 of nt=2ntp ; b0,b1 of nt=2ntp+1}
// Accumulator acc[mi][j][r]: row = wm*32 + mi*16 + g + 8*(r>>1),
//                            col = (wn*8+j)*8 + 2*tg + (r&1)
// ---------------------------------------------------------------------------
struct EdgeSmem {
    uint4    Wf[8 * 8 * 32];         // 32768 B  W fp16 fragments, j-paired
    uint32_t Af[4 * 8 * 132];        // 16896 B  A fp16 fragments (132-word blocks)
    uint32_t rb2[TM * 8];            //  2048 B  rbf as duplicated half2, 8-slot rows
    int kA[TM];
    int kB[TM];                      //   512 B
};                                   // 52224 B -> 4 CTAs/SM

__global__ __launch_bounds__(128, 4) void edge_kernel(
    const float* __restrict__ rbf,
    const int* __restrict__ gi,
    const int* __restrict__ gj,
    const float* __restrict__ rbf_w,
    const float* __restrict__ rbf_b,
    const float* __restrict__ lin_w,
    float* __restrict__ out) {
    extern __shared__ __align__(16) char smem_raw[];
    EdgeSmem& S = *reinterpret_cast<EdgeSmem*>(smem_raw);

    const int tid  = threadIdx.x;
    const int lane = tid & 31;
    const int wid  = tid >> 5;
    const int g    = lane >> 2;
    const int tg   = lane & 3;
    const int wm   = wid & 1;   // m-half (32 rows)
    const int wn   = wid >> 1;  // n-half (64 cols)

    // ---- stage W fragments (fp16), pre-permuted, j-paired uint4 ------------
    for (int e = tid; e < 8 * 8 * 32; e += 128) {
        const int ln = e & 31, ntp = (e >> 5) & 7, kc = e >> 8;
        const int nA = (2 * ntp) * 8 + (ln >> 2);
        const int k0 = kc * 16 + 2 * (ln & 3);
        const float* pA = lin_w + nA * 390 + 262 + k0;
        const float* pB = pA + 8 * 390;
        S.Wf[e] = make_uint4(pack_h2(pA[0], pA[1]), pack_h2(pA[8], pA[9]),
                             pack_h2(pB[0], pB[1]), pack_h2(pB[8], pB[9]));
    }

    // ---- per-thread rbf weights as half2 (cols k0=2c, k0+1; row half hh) ---
    const int c  = tid & 63;
    const int hh = tid >> 6;
    const int k0 = 2 * c;
    __half2 w2[RDIM];
#pragma unroll
    for (int q = 0; q < RDIM; q++)
        w2[q] = __floats2half2_rn(rbf_w[k0 * RDIM + q], rbf_w[(k0 + 1) * RDIM + q]);
    const __half2 b2 = __floats2half2_rn(rbf_b[k0], rbf_b[k0 + 1]);
    const __half2 halfc = __float2half2_rn(0.5f);
    // phase-2 A-fragment address pieces (fixed per thread)
    const int kc_t = c >> 3;
    const int p_t  = c & 7;
    const int tg_t = p_t & 3;
    const int pb_t = p_t >> 2;
    __syncthreads();

    for (int tile = blockIdx.x; tile < NTILES; tile += gridDim.x) {
        const int e0 = tile * TM;

        // -- phase 1: keys + rbf tile (as duplicated half2) -----------------
        if (tid < TM) {
            S.kA[tid] = g_key[__ldg(gi + e0 + tid)];
            S.kB[tid] = g_key[__ldg(gj + e0 + tid)];
        }
        for (int idx = tid; idx < TM * RDIM; idx += 128) {
            const float v = rbf[(size_t)e0 * RDIM + idx];
            __half2 d = __float2half2_rn(v);
            S.rb2[(idx / RDIM) * 8 + (idx % RDIM)] = *reinterpret_cast<uint32_t*>(&d);
        }
        __syncthreads();

        // -- phase 2: R = silu(rbf @ rbf_w^T + b), all-half2, direct frag ---
#pragma unroll 4
        for (int r = 0; r < 32; r++) {
            const int m = hh * 32 + r;
            const uint4 q03 = *reinterpret_cast<const uint4*>(&S.rb2[m * 8]);
            const uint2 q45 = *reinterpret_cast<const uint2*>(&S.rb2[m * 8 + 4]);
            __half2 z = b2;
            z = __hfma2(*reinterpret_cast<const __half2*>(&q03.x), w2[0], z);
            z = __hfma2(*reinterpret_cast<const __half2*>(&q03.y), w2[1], z);
            z = __hfma2(*reinterpret_cast<const __half2*>(&q03.z), w2[2], z);
            z = __hfma2(*reinterpret_cast<const __half2*>(&q03.w), w2[3], z);
            z = __hfma2(*reinterpret_cast<const __half2*>(&q45.x), w2[4], z);
            z = __hfma2(*reinterpret_cast<const __half2*>(&q45.y), w2[5], z);
            const __half2 s = __hmul2(z, halfc);
            const __half2 rr = __hfma2(s, tanh_h2(s), s);   // silu(z)
            const int mt = m >> 4, r16 = m & 15;
            const int hi = r16 >> 3, gg = r16 & 7;
            const int word = (mt * 8 + kc_t) * 132 + (gg * 4 + tg_t) * 4 + 2 * pb_t + hi;
            S.Af[word] = *reinterpret_cast<const uint32_t*>(&rr);
        }
        __syncthreads();

        // -- phase 3: GEMM, warp (wm,wn) does C[wm*32..+32][wn*64..+64] -----
        float acc[2][8][4];
#pragma unroll
        for (int mi = 0; mi < 2; mi++)
#pragma unroll
            for (int j = 0; j < 8; j++) {
                acc[mi][j][0] = 0.f; acc[mi][j][1] = 0.f;
                acc[mi][j][2] = 0.f; acc[mi][j][3] = 0.f;
            }
        const uint4* A4 = reinterpret_cast<const uint4*>(S.Af);
#pragma unroll
        for (int kc = 0; kc < 8; kc++) {
            const uint4 av0 = A4[((wm * 2 + 0) * 8 + kc) * 33 + lane];
            const uint4 av1 = A4[((wm * 2 + 1) * 8 + kc) * 33 + lane];
#pragma unroll
            for (int jp = 0; jp < 4; jp++) {
                const uint4 wv = S.Wf[(kc * 8 + wn * 4 + jp) * 32 + lane];
                mma_f16(acc[0][2 * jp],     av0.x, av0.y, av0.z, av0.w, wv.x, wv.y);
                mma_f16(acc[1][2 * jp],     av1.x, av1.y, av1.z, av1.w, wv.x, wv.y);
                mma_f16(acc[0][2 * jp + 1], av0.x, av0.y, av0.z, av0.w, wv.z, wv.w);
                mma_f16(acc[1][2 * jp + 1], av1.x, av1.y, av1.z, av1.w, wv.z, wv.w);
            }
        }

        // -- phase 4: epilogue straight from accumulators (fp16 tables) -----
#pragma unroll
        for (int mi = 0; mi < 2; mi++) {
#pragma unroll
            for (int hi = 0; hi < 2; hi++) {
                const int row = wm * 32 + mi * 16 + hi * 8 + g;
                const __half2* pa = reinterpret_cast<const __half2*>(g_tableA + S.kA[row] * H) + tg;
                const __half2* pb = reinterpret_cast<const __half2*>(g_tableB + S.kB[row] * H) + tg;
                float2* po = reinterpret_cast<float2*>(out + (size_t)(e0 + row) * H) + tg;
#pragma unroll
                for (int j = 0; j < 8; j++) {
                    const int ci = (wn * 8 + j) * 4;
                    const __half2 tsum = __hadd2(__ldg(pa + ci), __ldg(pb + ci));
                    const float2 tf = __half22float2(tsum);
                    float2 o;
                    o.x = silu_acc(tf.x + acc[mi][j][2 * hi + 0]);
                    o.y = silu_acc(tf.y + acc[mi][j][2 * hi + 1]);
                    po[ci] = o;
                }
            }
        }
        __syncthreads();   // protect kA/kB/rb2/Af before next tile overwrites
    }
}

// ---------------------------------------------------------------------------
extern "C" void kernel_launch(void* const* d_in, const int* in_sizes, int n_in,
                              void* d_out, int out_size) {
    const int*   x      = (const int*)d_in[0];
    const int*   s      = (const int*)d_in[1];
    const float* rbf    = (const float*)d_in[2];
    const int*   gi     = (const int*)d_in[3];
    const int*   gj     = (const int*)d_in[4];
    const float* emb_w  = (const float*)d_in[5];
    const float* spin_w = (const float*)d_in[6];
    const float* spin_b = (const float*)d_in[7];
    const float* rbf_w  = (const float*)d_in[8];
    const float* rbf_b  = (const float*)d_in[9];
    const float* lin_w  = (const float*)d_in[10];
    const float* lin_b  = (const float*)d_in[11];
    float* out = (float*)d_out;

    key_kernel<<<(N_NODES + 255) / 256, 256>>>(x, s);
    table_kernel<<<NKEYS, 128>>>(emb_w, spin_w, spin_b, lin_w, lin_b);

    const int smem = (int)sizeof(EdgeSmem);
    cudaFuncSetAttribute(edge_kernel, cudaFuncAttributeMaxDynamicSharedMemorySize, smem);
    edge_kernel<<<GRID, 128, smem>>>(rbf, gi, gj, rbf_w, rbf_b, lin_w, out);
}